// round 1
// baseline (speedup 1.0000x reference)
#include <cuda_runtime.h>
#include <cuda_bf16.h>

#define N_ATOMS 100000
#define E_ATOMS 200000
#define N_AMINO 10240
#define E_AMINO 20480
#define BGRAPH  512
#define D_IN    40
#define D_E     11
#define H       20
#define D_AA    8
#define F_IN    28      // H + D_AA
#define H_ARMA  128
#define K_ST    3
#define T_LAY   7
#define F1      256
#define F2      128
#define F3      64
#define NCOMB   260     // 220 (z) + 20 (xb) + 20 (acc init)

// ------------------------- scratch (device globals) -------------------------
__device__ float g_cn1[(long)N_ATOMS * NCOMB];
__device__ float g_cn2[(long)N_ATOMS * NCOMB];
__device__ float g_wpack[D_IN * NCOMB];
__device__ float g_bpack[NCOMB];
__device__ float g_aa[N_AMINO * F_IN];
__device__ float g_deg[N_AMINO];
__device__ float g_norm[E_AMINO];
__device__ float g_tmp [K_ST * N_AMINO * H_ARMA];
__device__ float g_accA[K_ST * N_AMINO * H_ARMA];
__device__ float g_accB[K_ST * N_AMINO * H_ARMA];
__device__ float g_pool[BGRAPH * H_ARMA];
__device__ float g_p1[BGRAPH * F1];
__device__ float g_p2[BGRAPH * F2];
__device__ float g_p3[BGRAPH * F3];

// ------------------------- generic small GEMM -------------------------
// C[b][m][n] = (bias[b][n]) + sum_k relu?(A[b][m][k]) * W[b][k][n]
// block: 32 rows, 256 threads, A tile staged in smem. N % 4 == 0 required.
__global__ void gemm_k(const float* __restrict__ A, int lda, long strideA,
                       const float* __restrict__ W, long strideW,
                       const float* __restrict__ B, long strideB,
                       float* __restrict__ C, int ldc, long strideC,
                       int M, int Kd, int N, int reluA)
{
    extern __shared__ float sA[];
    int b  = blockIdx.y;
    int m0 = blockIdx.x * 32;
    const float* Ab = A + (long)b * strideA;
    const float* Wb = W + (long)b * strideW;
    const float* Bb = B ? (B + (long)b * strideB) : nullptr;
    float*       Cb = C + (long)b * strideC;

    for (int idx = threadIdx.x; idx < 32 * Kd; idx += blockDim.x) {
        int r = idx / Kd, c = idx % Kd;
        int row = m0 + r;
        float v = (row < M) ? Ab[(long)row * lda + c] : 0.f;
        if (reluA) v = fmaxf(v, 0.f);
        sA[idx] = v;
    }
    __syncthreads();

    int ncols4 = N >> 2;
    int tot = 32 * ncols4;
    for (int oi = threadIdx.x; oi < tot; oi += blockDim.x) {
        int r  = oi / ncols4;
        int n4 = (oi - r * ncols4) << 2;
        int row = m0 + r;
        if (row >= M) continue;
        float4 acc;
        if (Bb) acc = *(const float4*)(Bb + n4);
        else    acc = make_float4(0.f, 0.f, 0.f, 0.f);
        const float* sa = sA + r * Kd;
        for (int k = 0; k < Kd; k++) {
            float a = sa[k];
            float4 w = *(const float4*)(Wb + (long)k * N + n4);
            acc.x = fmaf(a, w.x, acc.x);
            acc.y = fmaf(a, w.y, acc.y);
            acc.z = fmaf(a, w.z, acc.z);
            acc.w = fmaf(a, w.w, acc.w);
        }
        *(float4*)(Cb + (long)row * ldc + n4) = acc;
    }
}

// ------------------------- NNConv helpers -------------------------
// pack combined weight: cols [0,220)=z-weights (permuted nn_w), [220,240)=nn_b
// as matrix, [240,260)=root. bias vector = zeros except last 20 = b.
__global__ void pack_nn(const float* __restrict__ nw, const float* __restrict__ nb,
                        const float* __restrict__ root, const float* __restrict__ b,
                        float* __restrict__ Wp, float* __restrict__ bp, int d_in)
{
    int idx = blockIdx.x * blockDim.x + threadIdx.x;
    int total = d_in * NCOMB;
    if (idx < total) {
        int i = idx / NCOMB, c = idx % NCOMB;
        float v;
        if (c < 220)      { int d = c / H, o = c % H; v = nw[d * (d_in * H) + i * H + o]; }
        else if (c < 240) { v = nb[i * H + (c - 220)]; }
        else              { v = root[i * H + (c - 240)]; }
        Wp[idx] = v;
    }
    if (idx < NCOMB) bp[idx] = (idx < 240) ? 0.f : b[idx - 240];
}

// per-edge message: msg[o] = xb_src[o] + sum_d ea[e,d] * z_src[d,o]; atomic into dst acc cols
__global__ void nnconv_edge(const int* __restrict__ ei, const float* __restrict__ ea,
                            float* __restrict__ Cn)
{
    long idx = (long)blockIdx.x * blockDim.x + threadIdx.x;
    if (idx >= (long)E_ATOMS * H) return;
    int e = (int)(idx / H), o = (int)(idx % H);
    int src = ei[e], dst = ei[E_ATOMS + e];
    const float* zrow = Cn + (long)src * NCOMB;
    float m = zrow[220 + o];
    const float* eav = ea + (long)e * D_E;
    #pragma unroll
    for (int d = 0; d < D_E; d++) m = fmaf(eav[d], zrow[d * H + o], m);
    atomicAdd(Cn + (long)dst * NCOMB + 240 + o, m);
}

// ------------------------- amino stage -------------------------
__global__ void aa_init(const float* __restrict__ feat, float* __restrict__ aa)
{
    int idx = blockIdx.x * blockDim.x + threadIdx.x;
    if (idx >= N_AMINO * F_IN) return;
    int n = idx / F_IN, c = idx % F_IN;
    aa[idx] = (c < H) ? 0.f : feat[n * D_AA + (c - H)];
}

__global__ void atom2aa(const float* __restrict__ Cn, const int* __restrict__ lab,
                        float* __restrict__ aa)
{
    long idx = (long)blockIdx.x * blockDim.x + threadIdx.x;
    if (idx >= (long)N_ATOMS * H) return;
    int n = (int)(idx / H), o = (int)(idx % H);
    float v = fmaxf(Cn[(long)n * NCOMB + 240 + o], 0.f);
    atomicAdd(&aa[lab[n] * F_IN + o], v);
}

__global__ void zero_k(float* __restrict__ p, long n)
{
    long idx = (long)blockIdx.x * blockDim.x + threadIdx.x;
    if (idx < n) p[idx] = 0.f;
}

__global__ void deg_count(const int* __restrict__ ei, float* __restrict__ deg)
{
    int e = blockIdx.x * blockDim.x + threadIdx.x;
    if (e < E_AMINO) atomicAdd(&deg[ei[E_AMINO + e]], 1.f);
}

__global__ void norm_k(const int* __restrict__ ei, const float* __restrict__ deg,
                       float* __restrict__ nrm)
{
    int e = blockIdx.x * blockDim.x + threadIdx.x;
    if (e >= E_AMINO) return;
    float ds = deg[ei[e]], dd = deg[ei[E_AMINO + e]];
    float a = (ds > 0.f) ? (1.f / sqrtf(ds)) : 0.f;
    float c = (dd > 0.f) ? (1.f / sqrtf(dd)) : 0.f;
    nrm[e] = a * c;
}

__global__ void arma_scatter(const int* __restrict__ ei, const float* __restrict__ nrm,
                             const float* __restrict__ tmp, float* __restrict__ acc)
{
    long idx = (long)blockIdx.x * blockDim.x + threadIdx.x;
    if (idx >= (long)K_ST * E_AMINO * H_ARMA) return;
    int o = (int)(idx & (H_ARMA - 1));
    long r = idx >> 7;
    int e = (int)(r % E_AMINO);
    int k = (int)(r / E_AMINO);
    int src = ei[e], dst = ei[E_AMINO + e];
    float v = tmp[((long)k * N_AMINO + src) * H_ARMA + o] * nrm[e];
    atomicAdd(&acc[((long)k * N_AMINO + dst) * H_ARMA + o], v);
}

__global__ void pool_k(const float* __restrict__ acc, const int* __restrict__ ab,
                       float* __restrict__ g)
{
    long idx = (long)blockIdx.x * blockDim.x + threadIdx.x;
    if (idx >= (long)N_AMINO * H_ARMA) return;
    int n = (int)(idx >> 7), o = (int)(idx & (H_ARMA - 1));
    float v = 0.f;
    #pragma unroll
    for (int k = 0; k < K_ST; k++)
        v += fmaxf(acc[((long)k * N_AMINO + n) * H_ARMA + o], 0.f);
    atomicAdd(&g[ab[n] * H_ARMA + o], v * (1.f / 3.f));
}

__global__ void final_k(const float* __restrict__ p3, const float* __restrict__ w,
                        const float* __restrict__ b, float* __restrict__ out)
{
    int i = blockIdx.x * blockDim.x + threadIdx.x;
    if (i >= BGRAPH) return;
    float s = b[0];
    #pragma unroll
    for (int f = 0; f < F3; f++) s = fmaf(fmaxf(p3[i * F3 + f], 0.f), w[f], s);
    out[i] = s;
}

// ------------------------- host orchestration -------------------------
static inline int ceil_div(long a, int b) { return (int)((a + b - 1) / b); }

extern "C" void kernel_launch(void* const* d_in, const int* in_sizes, int n_in,
                              void* d_out, int out_size)
{
    const float* x     = (const float*)d_in[0];
    const int*   ei    = (const int*)  d_in[1];
    const float* ea    = (const float*)d_in[2];
    const int*   lab   = (const int*)  d_in[3];
    const float* feat  = (const float*)d_in[4];
    const int*   aei   = (const int*)  d_in[5];
    const int*   ab    = (const int*)  d_in[6];
    const float* nn1_w = (const float*)d_in[7];
    const float* nn1_b = (const float*)d_in[8];
    const float* root1 = (const float*)d_in[9];
    const float* b1    = (const float*)d_in[10];
    const float* nn2_w = (const float*)d_in[11];
    const float* nn2_b = (const float*)d_in[12];
    const float* root2 = (const float*)d_in[13];
    const float* b2    = (const float*)d_in[14];
    const float* nn3_w = (const float*)d_in[15];
    const float* nn3_b = (const float*)d_in[16];
    const float* root3 = (const float*)d_in[17];
    const float* b3    = (const float*)d_in[18];
    const float* arma_init = (const float*)d_in[19];
    const float* arma_w    = (const float*)d_in[20];
    const float* arma_root = (const float*)d_in[21];
    const float* arma_bias = (const float*)d_in[22];
    const float* l1_w = (const float*)d_in[23];
    const float* l1_b = (const float*)d_in[24];
    const float* l2_w = (const float*)d_in[25];
    const float* l2_b = (const float*)d_in[26];
    const float* l3_w = (const float*)d_in[27];
    const float* l3_b = (const float*)d_in[28];
    const float* l4_w = (const float*)d_in[29];
    const float* l4_b = (const float*)d_in[30];

    float *cn1, *cn2, *wp, *bp, *aa, *deg, *nrm, *tmp, *accA, *accB, *pool, *p1, *p2, *p3;
    cudaGetSymbolAddress((void**)&cn1,  g_cn1);
    cudaGetSymbolAddress((void**)&cn2,  g_cn2);
    cudaGetSymbolAddress((void**)&wp,   g_wpack);
    cudaGetSymbolAddress((void**)&bp,   g_bpack);
    cudaGetSymbolAddress((void**)&aa,   g_aa);
    cudaGetSymbolAddress((void**)&deg,  g_deg);
    cudaGetSymbolAddress((void**)&nrm,  g_norm);
    cudaGetSymbolAddress((void**)&tmp,  g_tmp);
    cudaGetSymbolAddress((void**)&accA, g_accA);
    cudaGetSymbolAddress((void**)&accB, g_accB);
    cudaGetSymbolAddress((void**)&pool, g_pool);
    cudaGetSymbolAddress((void**)&p1,   g_p1);
    cudaGetSymbolAddress((void**)&p2,   g_p2);
    cudaGetSymbolAddress((void**)&p3,   g_p3);

    const int TB = 256;
    dim3 gAtoms(ceil_div(N_ATOMS, 32), 1);
    int edgeBlocks = ceil_div((long)E_ATOMS * H, TB);

    // ---- NNConv layer 1 (input x, d_in=40) ----
    pack_nn<<<ceil_div(D_IN * NCOMB, TB), TB>>>(nn1_w, nn1_b, root1, b1, wp, bp, D_IN);
    gemm_k<<<gAtoms, TB, 32 * D_IN * sizeof(float)>>>(
        x, D_IN, 0, wp, 0, bp, 0, cn1, NCOMB, 0, N_ATOMS, D_IN, NCOMB, 0);
    nnconv_edge<<<edgeBlocks, TB>>>(ei, ea, cn1);

    // ---- NNConv layer 2 (input relu(acc1), d_in=20) ----
    pack_nn<<<ceil_div(H * NCOMB, TB), TB>>>(nn2_w, nn2_b, root2, b2, wp, bp, H);
    gemm_k<<<gAtoms, TB, 32 * H * sizeof(float)>>>(
        cn1 + 240, NCOMB, 0, wp, 0, bp, 0, cn2, NCOMB, 0, N_ATOMS, H, NCOMB, 1);
    nnconv_edge<<<edgeBlocks, TB>>>(ei, ea, cn2);

    // ---- NNConv layer 3 ----
    pack_nn<<<ceil_div(H * NCOMB, TB), TB>>>(nn3_w, nn3_b, root3, b3, wp, bp, H);
    gemm_k<<<gAtoms, TB, 32 * H * sizeof(float)>>>(
        cn2 + 240, NCOMB, 0, wp, 0, bp, 0, cn1, NCOMB, 0, N_ATOMS, H, NCOMB, 1);
    nnconv_edge<<<edgeBlocks, TB>>>(ei, ea, cn1);

    // ---- atoms -> amino ----
    aa_init<<<ceil_div(N_AMINO * F_IN, TB), TB>>>(feat, aa);
    atom2aa<<<ceil_div((long)N_ATOMS * H, TB), TB>>>(cn1, lab, aa);

    // ---- ARMA normalization ----
    zero_k<<<ceil_div(N_AMINO, TB), TB>>>(deg, N_AMINO);
    deg_count<<<ceil_div(E_AMINO, TB), TB>>>(aei, deg);
    norm_k<<<ceil_div(E_AMINO, TB), TB>>>(aei, deg, nrm);

    // ---- ARMA loop: K=3 stacks, T=7 layers ----
    dim3 gArma(ceil_div(N_AMINO, 32), K_ST);
    int scatterBlocks = ceil_div((long)K_ST * E_AMINO * H_ARMA, TB);
    float* accP = accA;
    float* accN = accB;
    for (int t = 0; t < T_LAY; t++) {
        if (t == 0) {
            gemm_k<<<gArma, TB, 32 * F_IN * sizeof(float)>>>(
                aa, F_IN, 0,
                arma_init, (long)F_IN * H_ARMA,
                nullptr, 0,
                tmp, H_ARMA, (long)N_AMINO * H_ARMA,
                N_AMINO, F_IN, H_ARMA, 0);
        } else {
            gemm_k<<<gArma, TB, 32 * H_ARMA * sizeof(float)>>>(
                accP, H_ARMA, (long)N_AMINO * H_ARMA,
                arma_w + (long)(t - 1) * K_ST * H_ARMA * H_ARMA, (long)H_ARMA * H_ARMA,
                nullptr, 0,
                tmp, H_ARMA, (long)N_AMINO * H_ARMA,
                N_AMINO, H_ARMA, H_ARMA, 1);
        }
        // acc = aa @ root[t] + bias[t]
        gemm_k<<<gArma, TB, 32 * F_IN * sizeof(float)>>>(
            aa, F_IN, 0,
            arma_root + (long)t * K_ST * F_IN * H_ARMA, (long)F_IN * H_ARMA,
            arma_bias + (long)t * K_ST * H_ARMA, H_ARMA,
            accN, H_ARMA, (long)N_AMINO * H_ARMA,
            N_AMINO, F_IN, H_ARMA, 0);
        arma_scatter<<<scatterBlocks, TB>>>(aei, nrm, tmp, accN);
        float* t2 = accP; accP = accN; accN = t2;
    }

    // ---- pooling over graphs (mean over K stacks + relu folded in) ----
    zero_k<<<ceil_div(BGRAPH * H_ARMA, TB), TB>>>(pool, (long)BGRAPH * H_ARMA);
    pool_k<<<ceil_div((long)N_AMINO * H_ARMA, TB), TB>>>(accP, ab, pool);

    // ---- FCN head ----
    dim3 gB(ceil_div(BGRAPH, 32), 1);
    gemm_k<<<gB, TB, 32 * H_ARMA * sizeof(float)>>>(
        pool, H_ARMA, 0, l1_w, 0, l1_b, 0, p1, F1, 0, BGRAPH, H_ARMA, F1, 0);
    gemm_k<<<gB, TB, 32 * F1 * sizeof(float)>>>(
        p1, F1, 0, l2_w, 0, l2_b, 0, p2, F2, 0, BGRAPH, F1, F2, 1);
    gemm_k<<<gB, TB, 32 * F2 * sizeof(float)>>>(
        p2, F2, 0, l3_w, 0, l3_b, 0, p3, F3, 0, BGRAPH, F2, F3, 1);
    final_k<<<ceil_div(BGRAPH, TB), TB>>>(p3, l4_w, l4_b, (float*)d_out);
}

// round 2
// speedup vs baseline: 1.6364x; 1.6364x over previous
#include <cuda_runtime.h>
#include <cuda_bf16.h>

#define N_ATOMS 100000
#define E_ATOMS 200000
#define N_AMINO 10240
#define E_AMINO 20480
#define BGRAPH  512
#define D_IN    40
#define D_E     11
#define H       20
#define D_AA    8
#define F_IN    28      // H + D_AA
#define H_ARMA  128
#define K_ST    3
#define T_LAY   7
#define F1      256
#define F2      128
#define F3      64
#define NCOMB   260     // 220 (z) + 20 (xb) + 20 (acc init)

// ------------------------- scratch (device globals) -------------------------
__device__ float g_cn1[(long)N_ATOMS * NCOMB];
__device__ float g_cn2[(long)N_ATOMS * NCOMB];
__device__ float g_wpack[D_IN * NCOMB];
__device__ float g_bpack[NCOMB];
__device__ float g_aa[N_AMINO * F_IN];
__device__ float g_deg[N_AMINO];
__device__ float g_norm[E_AMINO];
__device__ float g_tmp [K_ST * N_AMINO * H_ARMA];
__device__ float g_accA[K_ST * N_AMINO * H_ARMA];
__device__ float g_accB[K_ST * N_AMINO * H_ARMA];
__device__ float g_pool[BGRAPH * H_ARMA];
__device__ float g_p1[BGRAPH * F1];
__device__ float g_p2[BGRAPH * F2];
__device__ float g_p3[BGRAPH * F3];

// ------------------------- register-tiled GEMM -------------------------
// C[b][m][n] = bias[b][n] + sum_k relu?(A[b][m][k]) * W[b][k][n]
// BM=128, BN=64, 128 threads, 8x8 register tile per thread.
// Requires Kd % 4 == 0. smem = (BM*(Kd+1) + Kd*BN)*4 bytes.
__global__ void __launch_bounds__(128) gemm_tiled(
        const float* __restrict__ A, int lda, long strideA,
        const float* __restrict__ W, long strideW,
        const float* __restrict__ Bias, long strideB,
        float* __restrict__ C, int ldc, long strideC,
        int M, int Kd, int N, int reluA)
{
    const int BM = 128, BN = 64;
    extern __shared__ float sh[];
    const int ldsa = Kd + 1;
    float* sA = sh;                 // [BM][ldsa]
    float* sW = sh + BM * ldsa;     // [Kd][BN]

    int b = blockIdx.z;
    const float* Ab = A + (long)b * strideA;
    const float* Wb = W + (long)b * strideW;
    float*       Cb = C + (long)b * strideC;
    int m0 = blockIdx.x * BM;
    int n0 = blockIdx.y * BN;
    int tid = threadIdx.x;

    // stage W tile [Kd][BN] (zero-pad n >= N)
    int wtot = Kd * (BN / 4);
    for (int idx = tid; idx < wtot; idx += 128) {
        int k  = idx >> 4;            // BN/4 = 16
        int n4 = (idx & 15) << 2;
        int n  = n0 + n4;
        float4 w;
        const float* wr = Wb + (long)k * N;
        if (n + 3 < N) {
            w = *(const float4*)(wr + n);
        } else {
            w.x = (n     < N) ? wr[n]     : 0.f;
            w.y = (n + 1 < N) ? wr[n + 1] : 0.f;
            w.z = (n + 2 < N) ? wr[n + 2] : 0.f;
            w.w = (n + 3 < N) ? wr[n + 3] : 0.f;
        }
        *(float4*)(sW + k * BN + n4) = w;
    }

    // stage A tile [BM][Kd], relu fused, zero-pad rows >= M
    int kq = Kd >> 2;
    int atot = BM * kq;
    for (int idx = tid; idx < atot; idx += 128) {
        int m  = idx / kq;
        int k4 = (idx - m * kq) << 2;
        int row = m0 + m;
        float4 a = make_float4(0.f, 0.f, 0.f, 0.f);
        if (row < M) a = *(const float4*)(Ab + (long)row * lda + k4);
        if (reluA) {
            a.x = fmaxf(a.x, 0.f); a.y = fmaxf(a.y, 0.f);
            a.z = fmaxf(a.z, 0.f); a.w = fmaxf(a.w, 0.f);
        }
        float* d = sA + m * ldsa + k4;
        d[0] = a.x; d[1] = a.y; d[2] = a.z; d[3] = a.w;
    }
    __syncthreads();

    int ct = tid & 7;         // col-thread 0..7  -> cols nb..nb+7
    int rt = tid >> 3;        // row-thread 0..15 -> rows mbase..mbase+7
    int mbase = rt * 8;
    int nb = ct * 8;

    float acc[8][8];
    #pragma unroll
    for (int i = 0; i < 8; i++)
        #pragma unroll
        for (int j = 0; j < 8; j++) acc[i][j] = 0.f;

    const float* pW = sW + nb;
    const float* pA = sA + mbase * ldsa;
    for (int k = 0; k < Kd; k++) {
        float4 w0 = *(const float4*)(pW + k * BN);
        float4 w1 = *(const float4*)(pW + k * BN + 4);
        #pragma unroll
        for (int i = 0; i < 8; i++) {
            float a = pA[i * ldsa + k];
            acc[i][0] = fmaf(a, w0.x, acc[i][0]);
            acc[i][1] = fmaf(a, w0.y, acc[i][1]);
            acc[i][2] = fmaf(a, w0.z, acc[i][2]);
            acc[i][3] = fmaf(a, w0.w, acc[i][3]);
            acc[i][4] = fmaf(a, w1.x, acc[i][4]);
            acc[i][5] = fmaf(a, w1.y, acc[i][5]);
            acc[i][6] = fmaf(a, w1.z, acc[i][6]);
            acc[i][7] = fmaf(a, w1.w, acc[i][7]);
        }
    }

    // epilogue: bias + store
    float bv[8];
    #pragma unroll
    for (int j = 0; j < 8; j++) {
        int n = n0 + nb + j;
        bv[j] = (Bias && n < N) ? Bias[(long)b * strideB + n] : 0.f;
    }
    bool fullN = (n0 + nb + 7) < N;
    #pragma unroll
    for (int i = 0; i < 8; i++) {
        int row = m0 + mbase + i;
        if (row >= M) break;
        float* cr = Cb + (long)row * ldc + n0 + nb;
        if (fullN) {
            float4 o0 = make_float4(acc[i][0]+bv[0], acc[i][1]+bv[1], acc[i][2]+bv[2], acc[i][3]+bv[3]);
            float4 o1 = make_float4(acc[i][4]+bv[4], acc[i][5]+bv[5], acc[i][6]+bv[6], acc[i][7]+bv[7]);
            *(float4*)(cr)     = o0;
            *(float4*)(cr + 4) = o1;
        } else {
            #pragma unroll
            for (int j = 0; j < 8; j++) {
                int n = n0 + nb + j;
                if (n < N) cr[j] = acc[i][j] + bv[j];
            }
        }
    }
}

// ------------------------- NNConv helpers -------------------------
__global__ void pack_nn(const float* __restrict__ nw, const float* __restrict__ nb,
                        const float* __restrict__ root, const float* __restrict__ b,
                        float* __restrict__ Wp, float* __restrict__ bp, int d_in)
{
    int idx = blockIdx.x * blockDim.x + threadIdx.x;
    int total = d_in * NCOMB;
    if (idx < total) {
        int i = idx / NCOMB, c = idx % NCOMB;
        float v;
        if (c < 220)      { int d = c / H, o = c % H; v = nw[d * (d_in * H) + i * H + o]; }
        else if (c < 240) { v = nb[i * H + (c - 220)]; }
        else              { v = root[i * H + (c - 240)]; }
        Wp[idx] = v;
    }
    if (idx < NCOMB) bp[idx] = (idx < 240) ? 0.f : b[idx - 240];
}

__global__ void nnconv_edge(const int* __restrict__ ei, const float* __restrict__ ea,
                            float* __restrict__ Cn)
{
    long idx = (long)blockIdx.x * blockDim.x + threadIdx.x;
    if (idx >= (long)E_ATOMS * H) return;
    int e = (int)(idx / H), o = (int)(idx % H);
    int src = ei[e], dst = ei[E_ATOMS + e];
    const float* zrow = Cn + (long)src * NCOMB;
    float m = zrow[220 + o];
    const float* eav = ea + (long)e * D_E;
    #pragma unroll
    for (int d = 0; d < D_E; d++) m = fmaf(eav[d], zrow[d * H + o], m);
    atomicAdd(Cn + (long)dst * NCOMB + 240 + o, m);
}

// ------------------------- amino stage -------------------------
__global__ void aa_init(const float* __restrict__ feat, float* __restrict__ aa)
{
    int idx = blockIdx.x * blockDim.x + threadIdx.x;
    if (idx >= N_AMINO * F_IN) return;
    int n = idx / F_IN, c = idx % F_IN;
    aa[idx] = (c < H) ? 0.f : feat[n * D_AA + (c - H)];
}

__global__ void atom2aa(const float* __restrict__ Cn, const int* __restrict__ lab,
                        float* __restrict__ aa)
{
    long idx = (long)blockIdx.x * blockDim.x + threadIdx.x;
    if (idx >= (long)N_ATOMS * H) return;
    int n = (int)(idx / H), o = (int)(idx % H);
    float v = fmaxf(Cn[(long)n * NCOMB + 240 + o], 0.f);
    atomicAdd(&aa[lab[n] * F_IN + o], v);
}

__global__ void zero_k(float* __restrict__ p, long n)
{
    long idx = (long)blockIdx.x * blockDim.x + threadIdx.x;
    if (idx < n) p[idx] = 0.f;
}

__global__ void deg_count(const int* __restrict__ ei, float* __restrict__ deg)
{
    int e = blockIdx.x * blockDim.x + threadIdx.x;
    if (e < E_AMINO) atomicAdd(&deg[ei[E_AMINO + e]], 1.f);
}

__global__ void norm_k(const int* __restrict__ ei, const float* __restrict__ deg,
                       float* __restrict__ nrm)
{
    int e = blockIdx.x * blockDim.x + threadIdx.x;
    if (e >= E_AMINO) return;
    float ds = deg[ei[e]], dd = deg[ei[E_AMINO + e]];
    float a = (ds > 0.f) ? (1.f / sqrtf(ds)) : 0.f;
    float c = (dd > 0.f) ? (1.f / sqrtf(dd)) : 0.f;
    nrm[e] = a * c;
}

__global__ void arma_scatter(const int* __restrict__ ei, const float* __restrict__ nrm,
                             const float* __restrict__ tmp, float* __restrict__ acc)
{
    long idx = (long)blockIdx.x * blockDim.x + threadIdx.x;
    if (idx >= (long)K_ST * E_AMINO * H_ARMA) return;
    int o = (int)(idx & (H_ARMA - 1));
    long r = idx >> 7;
    int e = (int)(r % E_AMINO);
    int k = (int)(r / E_AMINO);
    int src = ei[e], dst = ei[E_AMINO + e];
    float v = tmp[((long)k * N_AMINO + src) * H_ARMA + o] * nrm[e];
    atomicAdd(&acc[((long)k * N_AMINO + dst) * H_ARMA + o], v);
}

__global__ void pool_k(const float* __restrict__ acc, const int* __restrict__ ab,
                       float* __restrict__ g)
{
    long idx = (long)blockIdx.x * blockDim.x + threadIdx.x;
    if (idx >= (long)N_AMINO * H_ARMA) return;
    int n = (int)(idx >> 7), o = (int)(idx & (H_ARMA - 1));
    float v = 0.f;
    #pragma unroll
    for (int k = 0; k < K_ST; k++)
        v += fmaxf(acc[((long)k * N_AMINO + n) * H_ARMA + o], 0.f);
    atomicAdd(&g[ab[n] * H_ARMA + o], v * (1.f / 3.f));
}

__global__ void final_k(const float* __restrict__ p3, const float* __restrict__ w,
                        const float* __restrict__ b, float* __restrict__ out)
{
    int i = blockIdx.x * blockDim.x + threadIdx.x;
    if (i >= BGRAPH) return;
    float s = b[0];
    #pragma unroll
    for (int f = 0; f < F3; f++) s = fmaf(fmaxf(p3[i * F3 + f], 0.f), w[f], s);
    out[i] = s;
}

// ------------------------- host orchestration -------------------------
static inline int ceil_div(long a, int b) { return (int)((a + b - 1) / b); }
static inline size_t gemm_smem(int Kd) { return (size_t)(128 * (Kd + 1) + Kd * 64) * sizeof(float); }

extern "C" void kernel_launch(void* const* d_in, const int* in_sizes, int n_in,
                              void* d_out, int out_size)
{
    const float* x     = (const float*)d_in[0];
    const int*   ei    = (const int*)  d_in[1];
    const float* ea    = (const float*)d_in[2];
    const int*   lab   = (const int*)  d_in[3];
    const float* feat  = (const float*)d_in[4];
    const int*   aei   = (const int*)  d_in[5];
    const int*   ab    = (const int*)  d_in[6];
    const float* nn1_w = (const float*)d_in[7];
    const float* nn1_b = (const float*)d_in[8];
    const float* root1 = (const float*)d_in[9];
    const float* b1    = (const float*)d_in[10];
    const float* nn2_w = (const float*)d_in[11];
    const float* nn2_b = (const float*)d_in[12];
    const float* root2 = (const float*)d_in[13];
    const float* b2    = (const float*)d_in[14];
    const float* nn3_w = (const float*)d_in[15];
    const float* nn3_b = (const float*)d_in[16];
    const float* root3 = (const float*)d_in[17];
    const float* b3    = (const float*)d_in[18];
    const float* arma_init = (const float*)d_in[19];
    const float* arma_w    = (const float*)d_in[20];
    const float* arma_root = (const float*)d_in[21];
    const float* arma_bias = (const float*)d_in[22];
    const float* l1_w = (const float*)d_in[23];
    const float* l1_b = (const float*)d_in[24];
    const float* l2_w = (const float*)d_in[25];
    const float* l2_b = (const float*)d_in[26];
    const float* l3_w = (const float*)d_in[27];
    const float* l3_b = (const float*)d_in[28];
    const float* l4_w = (const float*)d_in[29];
    const float* l4_b = (const float*)d_in[30];

    float *cn1, *cn2, *wp, *bp, *aa, *deg, *nrm, *tmp, *accA, *accB, *pool, *p1, *p2, *p3;
    cudaGetSymbolAddress((void**)&cn1,  g_cn1);
    cudaGetSymbolAddress((void**)&cn2,  g_cn2);
    cudaGetSymbolAddress((void**)&wp,   g_wpack);
    cudaGetSymbolAddress((void**)&bp,   g_bpack);
    cudaGetSymbolAddress((void**)&aa,   g_aa);
    cudaGetSymbolAddress((void**)&deg,  g_deg);
    cudaGetSymbolAddress((void**)&nrm,  g_norm);
    cudaGetSymbolAddress((void**)&tmp,  g_tmp);
    cudaGetSymbolAddress((void**)&accA, g_accA);
    cudaGetSymbolAddress((void**)&accB, g_accB);
    cudaGetSymbolAddress((void**)&pool, g_pool);
    cudaGetSymbolAddress((void**)&p1,   g_p1);
    cudaGetSymbolAddress((void**)&p2,   g_p2);
    cudaGetSymbolAddress((void**)&p3,   g_p3);

    // allow big dynamic smem (K up to 256 in head layer 2)
    cudaFuncSetAttribute(gemm_tiled, cudaFuncAttributeMaxDynamicSharedMemorySize, 210 * 1024);

    const int TB = 256;
    int edgeBlocks = ceil_div((long)E_ATOMS * H, TB);

    dim3 gN1(ceil_div(N_ATOMS, 128), ceil_div(NCOMB, 64), 1);   // (782, 5)

    // ---- NNConv layer 1 (input x, d_in=40) ----
    pack_nn<<<ceil_div(D_IN * NCOMB, TB), TB>>>(nn1_w, nn1_b, root1, b1, wp, bp, D_IN);
    gemm_tiled<<<gN1, 128, gemm_smem(D_IN)>>>(
        x, D_IN, 0, wp, 0, bp, 0, cn1, NCOMB, 0, N_ATOMS, D_IN, NCOMB, 0);
    nnconv_edge<<<edgeBlocks, TB>>>(ei, ea, cn1);

    // ---- NNConv layer 2 (input relu(acc1), d_in=20) ----
    pack_nn<<<ceil_div(H * NCOMB, TB), TB>>>(nn2_w, nn2_b, root2, b2, wp, bp, H);
    gemm_tiled<<<gN1, 128, gemm_smem(H)>>>(
        cn1 + 240, NCOMB, 0, wp, 0, bp, 0, cn2, NCOMB, 0, N_ATOMS, H, NCOMB, 1);
    nnconv_edge<<<edgeBlocks, TB>>>(ei, ea, cn2);

    // ---- NNConv layer 3 ----
    pack_nn<<<ceil_div(H * NCOMB, TB), TB>>>(nn3_w, nn3_b, root3, b3, wp, bp, H);
    gemm_tiled<<<gN1, 128, gemm_smem(H)>>>(
        cn2 + 240, NCOMB, 0, wp, 0, bp, 0, cn1, NCOMB, 0, N_ATOMS, H, NCOMB, 1);
    nnconv_edge<<<edgeBlocks, TB>>>(ei, ea, cn1);

    // ---- atoms -> amino ----
    aa_init<<<ceil_div(N_AMINO * F_IN, TB), TB>>>(feat, aa);
    atom2aa<<<ceil_div((long)N_ATOMS * H, TB), TB>>>(cn1, lab, aa);

    // ---- ARMA normalization ----
    zero_k<<<ceil_div(N_AMINO, TB), TB>>>(deg, N_AMINO);
    deg_count<<<ceil_div(E_AMINO, TB), TB>>>(aei, deg);
    norm_k<<<ceil_div(E_AMINO, TB), TB>>>(aei, deg, nrm);

    // ---- ARMA loop: K=3 stacks, T=7 layers ----
    dim3 gArma(ceil_div(N_AMINO, 128), 2, K_ST);   // (80, 2, 3)
    int scatterBlocks = ceil_div((long)K_ST * E_AMINO * H_ARMA, TB);
    float* accP = accA;
    float* accN = accB;
    for (int t = 0; t < T_LAY; t++) {
        if (t == 0) {
            gemm_tiled<<<gArma, 128, gemm_smem(F_IN)>>>(
                aa, F_IN, 0,
                arma_init, (long)F_IN * H_ARMA,
                nullptr, 0,
                tmp, H_ARMA, (long)N_AMINO * H_ARMA,
                N_AMINO, F_IN, H_ARMA, 0);
        } else {
            gemm_tiled<<<gArma, 128, gemm_smem(H_ARMA)>>>(
                accP, H_ARMA, (long)N_AMINO * H_ARMA,
                arma_w + (long)(t - 1) * K_ST * H_ARMA * H_ARMA, (long)H_ARMA * H_ARMA,
                nullptr, 0,
                tmp, H_ARMA, (long)N_AMINO * H_ARMA,
                N_AMINO, H_ARMA, H_ARMA, 1);
        }
        // acc = aa @ root[t] + bias[t]
        gemm_tiled<<<gArma, 128, gemm_smem(F_IN)>>>(
            aa, F_IN, 0,
            arma_root + (long)t * K_ST * F_IN * H_ARMA, (long)F_IN * H_ARMA,
            arma_bias + (long)t * K_ST * H_ARMA, H_ARMA,
            accN, H_ARMA, (long)N_AMINO * H_ARMA,
            N_AMINO, F_IN, H_ARMA, 0);
        arma_scatter<<<scatterBlocks, TB>>>(aei, nrm, tmp, accN);
        float* t2 = accP; accP = accN; accN = t2;
    }

    // ---- pooling over graphs (mean over K stacks + relu folded in) ----
    zero_k<<<ceil_div(BGRAPH * H_ARMA, TB), TB>>>(pool, (long)BGRAPH * H_ARMA);
    pool_k<<<ceil_div((long)N_AMINO * H_ARMA, TB), TB>>>(accP, ab, pool);

    // ---- FCN head ----
    dim3 gH1(ceil_div(BGRAPH, 128), ceil_div(F1, 64), 1);
    gemm_tiled<<<gH1, 128, gemm_smem(H_ARMA)>>>(
        pool, H_ARMA, 0, l1_w, 0, l1_b, 0, p1, F1, 0, BGRAPH, H_ARMA, F1, 0);
    dim3 gH2(ceil_div(BGRAPH, 128), ceil_div(F2, 64), 1);
    gemm_tiled<<<gH2, 128, gemm_smem(F1)>>>(
        p1, F1, 0, l2_w, 0, l2_b, 0, p2, F2, 0, BGRAPH, F1, F2, 1);
    dim3 gH3(ceil_div(BGRAPH, 128), ceil_div(F3, 64), 1);
    gemm_tiled<<<gH3, 128, gemm_smem(F2)>>>(
        p2, F2, 0, l3_w, 0, l3_b, 0, p3, F3, 0, BGRAPH, F2, F3, 1);
    final_k<<<ceil_div(BGRAPH, TB), TB>>>(p3, l4_w, l4_b, (float*)d_out);
}